// round 13
// baseline (speedup 1.0000x reference)
#include <cuda_runtime.h>
#include <cuda_fp16.h>

#define RESO    128
#define NRAYS   16384
#define NSAMP   192
#define STEP    0.5f
#define NVOX    (RESO*RESO*RESO)
#define VPB     128     // voxels per repack block

// Padded fp16 grid: 32 halves = 64B per voxel (4 uint4).
// slots [0..26] = SH channels, [27] = density (fp16), [28..31] = zero padding.
__device__ uint4 g_grid4[NVOX * 4];     // NVOX * 64B

// ---------------------------------------------------------------------------
// Pass 0: fused repack (sh + density) -> fp16 padded layout via smem staging.
// Coalesced float4 reads, fully-coalesced uint4 (16B) writes.
// ---------------------------------------------------------------------------
__global__ void __launch_bounds__(256)
repack_grid(const float* __restrict__ sh, const float* __restrict__ density)
{
    __shared__ __half sm[VPB * 32];     // 8KB tile
    int tid = threadIdx.x;

    // zero padding slots [28..31] of each voxel record (slot 27 = density below)
    for (int i = tid; i < VPB * 4; i += 256) {
        int v = i >> 2, c = 28 + (i & 3);
        sm[v * 32 + c] = __ushort_as_half(0);
    }
    // density -> slot 27 (coalesced read, 1 float per voxel)
    if (tid < VPB) {
        float d = __ldg(density + (size_t)blockIdx.x * VPB + tid);
        sm[tid * 32 + 27] = __float2half(d);
    }

    // coalesced read + convert: 864 float4 per block
    const float4* src = (const float4*)(sh + (size_t)blockIdx.x * VPB * 27);
    for (int i = tid; i < VPB * 27 / 4; i += 256) {
        float4 f = __ldg(src + i);
        int flat = i * 4;
        int v = flat / 27;
        int c = flat - v * 27;
        float vals[4] = {f.x, f.y, f.z, f.w};
#pragma unroll
        for (int j = 0; j < 4; j++) {
            sm[v * 32 + c] = __float2half(vals[j]);
            if (++c == 27) { c = 0; ++v; }
        }
    }
    __syncthreads();

    // coalesced write-out: 512 uint4 per block (128B per 8 lanes)
    uint4* dst = g_grid4 + (size_t)blockIdx.x * (VPB * 4);
    const uint4* s4 = (const uint4*)sm;
    for (int i = tid; i < VPB * 4; i += 256)
        dst[i] = s4[i];
}

// ---------------------------------------------------------------------------
// Pass 1: render. One warp per ray; 8 samples in flight, 4 lanes per sample.
// Lane sub (0..3) loads channels [8sub..8sub+7] via one LDG.128 per corner
// (fp16 HFMA2 accumulation). 3-shuffle transpose-butterfly -> lane sub owns
// color sub; 3-step warp scan gives transmittance prefixes.
// Trip count computed analytically (ray-box exit + 2-sample margin; the exact
// per-sample inb predicate is retained, so classification is unchanged).
// T-cutoff checked on odd iterations only -> even->odd boundary has no
// data-dependent branch and unroll-2 pipelines loads over the reduce tail.
// ---------------------------------------------------------------------------
__global__ void __launch_bounds__(64, 14)
render_kernel(const float* __restrict__ origins,
              const float* __restrict__ dirs,
              float* __restrict__ out)
{
    const unsigned FULL = 0xFFFFFFFFu;
    int gw   = (blockIdx.x * blockDim.x + threadIdx.x) >> 5;   // ray id
    int lane = threadIdx.x & 31;
    if (gw >= NRAYS) return;
    int grp = lane >> 2;       // sample-in-flight (0..7)
    int sub = lane & 3;        // channel-octet slot / color owner (0..3)

    float ox = origins[gw*3+0], oy = origins[gw*3+1], oz = origins[gw*3+2];
    float dx = dirs[gw*3+0],    dy = dirs[gw*3+1],    dz = dirs[gw*3+2];

    // Analytic ray-box exit (origins are interior; box [0,127]^3).
    // Conservative margin of ~2 samples dwarfs the ~1e-4 divide error; the
    // exact inb check below keeps per-sample classification identical.
    float tx = (fabsf(dx) > 1e-9f) ? __fdividef((dx > 0.f ? 127.f : 0.f) - ox, dx) : 1e9f;
    float ty = (fabsf(dy) > 1e-9f) ? __fdividef((dy > 0.f ? 127.f : 0.f) - oy, dy) : 1e9f;
    float tz = (fabsf(dz) > 1e-9f) ? __fdividef((dz > 0.f ? 127.f : 0.f) - oz, dz) : 1e9f;
    float t_exit = fminf(tx, fminf(ty, tz));
    int   s_hi   = (int)(2.f * t_exit + 2.f);         // last possibly-in sample + margin
    int   n_it   = min(NSAMP / 8, (s_hi >> 3) + 1);   // warp-uniform trip count

    // Real SH degree-2 basis (svox2 convention)
    float basis[9];
    basis[0] =  0.28209479177387814f;
    basis[1] = -0.4886025119029199f * dy;
    basis[2] =  0.4886025119029199f * dz;
    basis[3] = -0.4886025119029199f * dx;
    basis[4] =  1.0925484305920792f * dx * dy;
    basis[5] = -1.0925484305920792f * dy * dz;
    basis[6] =  0.31539156525252005f * (2.f*dz*dz - dx*dx - dy*dy);
    basis[7] = -1.0925484305920792f * dx * dz;
    basis[8] =  0.5462742152960396f * (dx*dx - dy*dy);

    // Two-segment channel routing: lane sub owns channels [8sub..8sub+7],
    // spanning at most 2 consecutive colors (R<9, G<18, B<27, 27=sigma).
    float cA[8], cB[8];
    {
        int chA = 8*sub;
        int chB = min(8*sub + 7, 27);
        int colA = chA < 9 ? 0 : (chA < 18 ? 1 : (chA < 27 ? 2 : 3));
        int colB = chB < 9 ? 0 : (chB < 18 ? 1 : (chB < 27 ? 2 : 3));
#pragma unroll
        for (int m = 0; m < 8; m++) {
            int ch = 8*sub + m;
            int col = ch < 9 ? 0 : (ch < 18 ? 1 : (ch < 27 ? 2 : (ch == 27 ? 3 : -1)));
            float bk = (ch < 27) ? basis[ch % 9] : (ch == 27 ? 1.f : 0.f);
            cA[m] = (col == colA) ? bk : 0.f;
            cB[m] = (col == colB && colB != colA) ? bk : 0.f;
        }
        // sub0: A=R | sub1: A=R,B=G | sub2: A=G,B=B | sub3: A=B,B=sigma
    }

    const uint4* __restrict__ gh = g_grid4;   // voxel = 4 uint4

    float T = 1.f;
    float c_acc = 0.f;      // lane sub accumulates color sub (sub3: unused)

#pragma unroll 2
    for (int it = 0; it < n_it; ++it) {
        int   s = it*8 + grp;
        float t = ((float)s + 0.5f) * STEP;
        float px = fmaf(t, dx, ox);
        float py = fmaf(t, dy, oy);
        float pz = fmaf(t, dz, oz);
        bool inb = (px >= 0.f) && (px <= 127.f) &&
                   (py >= 0.f) && (py <= 127.f) &&
                   (pz >= 0.f) && (pz <= 127.f);

        float fx = floorf(px), fy = floorf(py), fz = floorf(pz);
        float rx = px - fx,    ry = py - fy,    rz = pz - fz;
        int ix = min(max((int)fx, 0), RESO - 2);
        int iy = min(max((int)fy, 0), RESO - 2);
        int iz = min(max((int)fz, 0), RESO - 2);
        float wx0 = 1.f - rx, wy0 = 1.f - ry, wz0 = 1.f - rz;

        __half2 acc0 = __float2half2_rn(0.f), acc1 = acc0;
        __half2 acc2 = acc0, acc3 = acc0;
        if (inb) {
            int vox = (((ix << 7) | iy) << 7) | iz;
            const uint4* p = gh + vox * 4 + sub;
#pragma unroll
            for (int c = 0; c < 8; ++c) {
                float w = ((c & 4) ? rx : wx0) *
                          ((c & 2) ? ry : wy0) *
                          ((c & 1) ? rz : wz0);
                __half2 wh = __float2half2_rn(w);
                uint4 u = __ldg(p + ((c & 4) ? (RESO*RESO*4) : 0)
                                  + ((c & 2) ? (RESO*4)      : 0)
                                  + ((c & 1) ? 4             : 0));
                acc0 = __hfma2(wh, *(const __half2*)&u.x, acc0);
                acc1 = __hfma2(wh, *(const __half2*)&u.y, acc1);
                acc2 = __hfma2(wh, *(const __half2*)&u.z, acc2);
                acc3 = __hfma2(wh, *(const __half2*)&u.w, acc3);
            }
        }
        float2 g0 = __half22float2(acc0);
        float2 g1 = __half22float2(acc1);
        float2 g2 = __half22float2(acc2);
        float2 g3 = __half22float2(acc3);
        float f0=g0.x, f1=g0.y, f2=g1.x, f3=g1.y, f4=g2.x, f5=g2.y, f6=g3.x, f7=g3.y;

        float pA = f0*cA[0]+f1*cA[1]+f2*cA[2]+f3*cA[3]+f4*cA[4]+f5*cA[5]+f6*cA[6]+f7*cA[7];
        float pB = f0*cB[0]+f1*cB[1]+f2*cB[2]+f3*cB[3]+f4*cB[4]+f5*cB[5]+f6*cB[6]+f7*cB[7];

        // Map segment partials to per-color contributions v0..v3 (R,G,B,sigma).
        float v0 = (sub <= 1) ? pA : 0.f;
        float v1 = (sub == 1) ? pB : ((sub == 2) ? pA : 0.f);
        float v2 = (sub == 2) ? pB : ((sub == 3) ? pA : 0.f);
        float v3 = (sub == 3) ? pB : 0.f;

        // Transpose-butterfly over the 4-lane group: lane sub ends with the
        // group total of v_sub. 3 shuffles.
        bool b0 = sub & 1, b1 = sub & 2;
        float sA = __shfl_xor_sync(FULL, b0 ? v0 : v1, 1);
        float A  = (b0 ? v1 : v0) + sA;
        float sB = __shfl_xor_sync(FULL, b0 ? v2 : v3, 1);
        float B  = (b0 ? v3 : v2) + sB;
        float sF = __shfl_xor_sync(FULL, b1 ? A : B, 2);
        float fin = (b1 ? B : A) + sF;           // lane sub: total of v_sub

        // sigma lives on sub==3 lanes (group-uniform inb).
        float sigma = (inb && fin > 1e-10f) ? fin : 0.f;
        float la = -sigma * STEP;                // valid on rep lanes (sub==3)

        // Inclusive scan of la over the 8 rep lanes (stride-4 aligned).
        float incl = la;
        float u1 = __shfl_up_sync(FULL, incl, 4);  if (lane >= 4)  incl += u1;
        float u2 = __shfl_up_sync(FULL, incl, 8);  if (lane >= 8)  incl += u2;
        float u3 = __shfl_up_sync(FULL, incl, 16); if (lane >= 16) incl += u3;
        float excl = incl - la;

        int rep = lane | 3;
        float pre   = __shfl_sync(FULL, excl, rep);   // prefix for own group
        float lself = __shfl_sync(FULL, la,   rep);   // own group's log-att
        float total = __shfl_sync(FULL, incl, 31);    // sum over all 8

        float e0 = __expf(pre);
        float e1 = __expf(pre + lself);
        float w  = T * (e0 - e1);                 // = T*exp(pre)*(1-exp(la))

        c_acc += (sub == 3) ? 0.f : w * fmaxf(fin + 0.5f, 0.f);
        T *= __expf(total);

        // T-cutoff on odd iterations only (leftover < ~2e-5 abs; extra
        // processed iterations are correctness-neutral).
        if ((it & 1) && T < 1e-5f) break;
    }

    // Sum each color across the 8 groups: lanes congruent mod 4 share a color.
    c_acc += __shfl_xor_sync(FULL, c_acc, 4);
    c_acc += __shfl_xor_sync(FULL, c_acc, 8);
    c_acc += __shfl_xor_sync(FULL, c_acc, 16);

    if (lane < 3)
        out[gw*3 + lane] = c_acc + T;   // + T_final * EMPTY_BRIGHT (=1)
}

// ---------------------------------------------------------------------------
extern "C" void kernel_launch(void* const* d_in, const int* in_sizes, int n_in,
                              void* d_out, int out_size)
{
    const float* origins = (const float*)d_in[0];   // [NRAYS,3]
    const float* dirs    = (const float*)d_in[1];   // [NRAYS,3]
    const float* density = (const float*)d_in[2];   // [128^3]
    const float* sh      = (const float*)d_in[3];   // [128^3,27]
    float* out = (float*)d_out;                     // [NRAYS,3]

    repack_grid<<<NVOX / VPB, 256>>>(sh, density);
    render_kernel<<<(NRAYS * 32) / 64, 64>>>(origins, dirs, out);
}

// round 14
// speedup vs baseline: 1.0542x; 1.0542x over previous
#include <cuda_runtime.h>
#include <cuda_fp16.h>

#define RESO    128
#define NRAYS   16384
#define NSAMP   192
#define STEP    0.5f
#define NVOX    (RESO*RESO*RESO)
#define VPB     128     // voxels per repack block

// Padded fp16 grid: 32 halves = 64B per voxel (4 uint4).
// slots [0..26] = SH channels, [27] = density (fp16), [28..31] = zero padding.
__device__ uint4 g_grid4[NVOX * 4];     // NVOX * 64B

// ---------------------------------------------------------------------------
// Pass 0: fused repack (sh + density) -> fp16 padded layout via smem staging.
// Coalesced float4 reads, fully-coalesced uint4 (16B) writes.
// ---------------------------------------------------------------------------
__global__ void __launch_bounds__(256)
repack_grid(const float* __restrict__ sh, const float* __restrict__ density)
{
    __shared__ __half sm[VPB * 32];     // 8KB tile
    int tid = threadIdx.x;

    // zero padding slots [28..31] of each voxel record (slot 27 = density below)
    for (int i = tid; i < VPB * 4; i += 256) {
        int v = i >> 2, c = 28 + (i & 3);
        sm[v * 32 + c] = __ushort_as_half(0);
    }
    // density -> slot 27 (coalesced read, 1 float per voxel)
    if (tid < VPB) {
        float d = __ldg(density + (size_t)blockIdx.x * VPB + tid);
        sm[tid * 32 + 27] = __float2half(d);
    }

    // coalesced read + convert: 864 float4 per block
    const float4* src = (const float4*)(sh + (size_t)blockIdx.x * VPB * 27);
    for (int i = tid; i < VPB * 27 / 4; i += 256) {
        float4 f = __ldg(src + i);
        int flat = i * 4;
        int v = flat / 27;
        int c = flat - v * 27;
        float vals[4] = {f.x, f.y, f.z, f.w};
#pragma unroll
        for (int j = 0; j < 4; j++) {
            sm[v * 32 + c] = __float2half(vals[j]);
            if (++c == 27) { c = 0; ++v; }
        }
    }
    __syncthreads();

    // coalesced write-out: 512 uint4 per block (128B per 8 lanes)
    uint4* dst = g_grid4 + (size_t)blockIdx.x * (VPB * 4);
    const uint4* s4 = (const uint4*)sm;
    for (int i = tid; i < VPB * 4; i += 256)
        dst[i] = s4[i];
}

// ---------------------------------------------------------------------------
// Pass 1: render. One warp per ray; 8 samples in flight, 4 lanes per sample.
// Lane sub (0..3) loads channels [8sub..8sub+7] via one LDG.128 per corner
// (fp16 HFMA2 accumulation). 3-shuffle transpose-butterfly -> lane sub owns
// color sub; 3-step warp scan gives transmittance prefixes.
// Trip count computed analytically (ray-box exit + margin; the exact
// per-sample inb predicate is retained, so classification is unchanged) --
// no per-iteration ballot. T-cutoff checked on odd iterations only.
// R12 launch config restored (no unroll-2; regs ~63, occ ~37%).
// ---------------------------------------------------------------------------
__global__ void __launch_bounds__(64, 16)
render_kernel(const float* __restrict__ origins,
              const float* __restrict__ dirs,
              float* __restrict__ out)
{
    const unsigned FULL = 0xFFFFFFFFu;
    int gw   = (blockIdx.x * blockDim.x + threadIdx.x) >> 5;   // ray id
    int lane = threadIdx.x & 31;
    if (gw >= NRAYS) return;
    int grp = lane >> 2;       // sample-in-flight (0..7)
    int sub = lane & 3;        // channel-octet slot / color owner (0..3)

    float ox = origins[gw*3+0], oy = origins[gw*3+1], oz = origins[gw*3+2];
    float dx = dirs[gw*3+0],    dy = dirs[gw*3+1],    dz = dirs[gw*3+2];

    // Analytic ray-box exit (origins are interior; box [0,127]^3).
    // Conservative ~2-sample margin dwarfs the ~1e-4 divide error; the exact
    // inb check below keeps per-sample classification identical.
    float tx = (fabsf(dx) > 1e-9f) ? __fdividef((dx > 0.f ? 127.f : 0.f) - ox, dx) : 1e9f;
    float ty = (fabsf(dy) > 1e-9f) ? __fdividef((dy > 0.f ? 127.f : 0.f) - oy, dy) : 1e9f;
    float tz = (fabsf(dz) > 1e-9f) ? __fdividef((dz > 0.f ? 127.f : 0.f) - oz, dz) : 1e9f;
    float t_exit = fminf(tx, fminf(ty, tz));
    int   s_hi   = (int)(2.f * t_exit + 2.f);         // last possibly-in sample + margin
    int   n_it   = min(NSAMP / 8, (s_hi >> 3) + 1);   // warp-uniform trip count

    // Real SH degree-2 basis (svox2 convention)
    float basis[9];
    basis[0] =  0.28209479177387814f;
    basis[1] = -0.4886025119029199f * dy;
    basis[2] =  0.4886025119029199f * dz;
    basis[3] = -0.4886025119029199f * dx;
    basis[4] =  1.0925484305920792f * dx * dy;
    basis[5] = -1.0925484305920792f * dy * dz;
    basis[6] =  0.31539156525252005f * (2.f*dz*dz - dx*dx - dy*dy);
    basis[7] = -1.0925484305920792f * dx * dz;
    basis[8] =  0.5462742152960396f * (dx*dx - dy*dy);

    // Two-segment channel routing: lane sub owns channels [8sub..8sub+7],
    // spanning at most 2 consecutive colors (R<9, G<18, B<27, 27=sigma).
    float cA[8], cB[8];
    {
        int chA = 8*sub;
        int chB = min(8*sub + 7, 27);
        int colA = chA < 9 ? 0 : (chA < 18 ? 1 : (chA < 27 ? 2 : 3));
        int colB = chB < 9 ? 0 : (chB < 18 ? 1 : (chB < 27 ? 2 : 3));
#pragma unroll
        for (int m = 0; m < 8; m++) {
            int ch = 8*sub + m;
            int col = ch < 9 ? 0 : (ch < 18 ? 1 : (ch < 27 ? 2 : (ch == 27 ? 3 : -1)));
            float bk = (ch < 27) ? basis[ch % 9] : (ch == 27 ? 1.f : 0.f);
            cA[m] = (col == colA) ? bk : 0.f;
            cB[m] = (col == colB && colB != colA) ? bk : 0.f;
        }
        // sub0: A=R | sub1: A=R,B=G | sub2: A=G,B=B | sub3: A=B,B=sigma
    }

    const uint4* __restrict__ gh = g_grid4;   // voxel = 4 uint4

    float T = 1.f;
    float c_acc = 0.f;      // lane sub accumulates color sub (sub3: unused)

    for (int it = 0; it < n_it; ++it) {
        int   s = it*8 + grp;
        float t = ((float)s + 0.5f) * STEP;
        float px = fmaf(t, dx, ox);
        float py = fmaf(t, dy, oy);
        float pz = fmaf(t, dz, oz);
        bool inb = (px >= 0.f) && (px <= 127.f) &&
                   (py >= 0.f) && (py <= 127.f) &&
                   (pz >= 0.f) && (pz <= 127.f);

        float fx = floorf(px), fy = floorf(py), fz = floorf(pz);
        float rx = px - fx,    ry = py - fy,    rz = pz - fz;
        int ix = min(max((int)fx, 0), RESO - 2);
        int iy = min(max((int)fy, 0), RESO - 2);
        int iz = min(max((int)fz, 0), RESO - 2);
        float wx0 = 1.f - rx, wy0 = 1.f - ry, wz0 = 1.f - rz;

        __half2 acc0 = __float2half2_rn(0.f), acc1 = acc0;
        __half2 acc2 = acc0, acc3 = acc0;
        if (inb) {
            int vox = (((ix << 7) | iy) << 7) | iz;
            const uint4* p = gh + vox * 4 + sub;
#pragma unroll
            for (int c = 0; c < 8; ++c) {
                float w = ((c & 4) ? rx : wx0) *
                          ((c & 2) ? ry : wy0) *
                          ((c & 1) ? rz : wz0);
                __half2 wh = __float2half2_rn(w);
                uint4 u = __ldg(p + ((c & 4) ? (RESO*RESO*4) : 0)
                                  + ((c & 2) ? (RESO*4)      : 0)
                                  + ((c & 1) ? 4             : 0));
                acc0 = __hfma2(wh, *(const __half2*)&u.x, acc0);
                acc1 = __hfma2(wh, *(const __half2*)&u.y, acc1);
                acc2 = __hfma2(wh, *(const __half2*)&u.z, acc2);
                acc3 = __hfma2(wh, *(const __half2*)&u.w, acc3);
            }
        }
        float2 g0 = __half22float2(acc0);
        float2 g1 = __half22float2(acc1);
        float2 g2 = __half22float2(acc2);
        float2 g3 = __half22float2(acc3);
        float f0=g0.x, f1=g0.y, f2=g1.x, f3=g1.y, f4=g2.x, f5=g2.y, f6=g3.x, f7=g3.y;

        float pA = f0*cA[0]+f1*cA[1]+f2*cA[2]+f3*cA[3]+f4*cA[4]+f5*cA[5]+f6*cA[6]+f7*cA[7];
        float pB = f0*cB[0]+f1*cB[1]+f2*cB[2]+f3*cB[3]+f4*cB[4]+f5*cB[5]+f6*cB[6]+f7*cB[7];

        // Map segment partials to per-color contributions v0..v3 (R,G,B,sigma).
        float v0 = (sub <= 1) ? pA : 0.f;
        float v1 = (sub == 1) ? pB : ((sub == 2) ? pA : 0.f);
        float v2 = (sub == 2) ? pB : ((sub == 3) ? pA : 0.f);
        float v3 = (sub == 3) ? pB : 0.f;

        // Transpose-butterfly over the 4-lane group: lane sub ends with the
        // group total of v_sub. 3 shuffles.
        bool b0 = sub & 1, b1 = sub & 2;
        float sA = __shfl_xor_sync(FULL, b0 ? v0 : v1, 1);
        float A  = (b0 ? v1 : v0) + sA;
        float sB = __shfl_xor_sync(FULL, b0 ? v2 : v3, 1);
        float B  = (b0 ? v3 : v2) + sB;
        float sF = __shfl_xor_sync(FULL, b1 ? A : B, 2);
        float fin = (b1 ? B : A) + sF;           // lane sub: total of v_sub

        // sigma lives on sub==3 lanes (group-uniform inb).
        float sigma = (inb && fin > 1e-10f) ? fin : 0.f;
        float la = -sigma * STEP;                // valid on rep lanes (sub==3)

        // Inclusive scan of la over the 8 rep lanes (stride-4 aligned).
        float incl = la;
        float u1 = __shfl_up_sync(FULL, incl, 4);  if (lane >= 4)  incl += u1;
        float u2 = __shfl_up_sync(FULL, incl, 8);  if (lane >= 8)  incl += u2;
        float u3 = __shfl_up_sync(FULL, incl, 16); if (lane >= 16) incl += u3;
        float excl = incl - la;

        int rep = lane | 3;
        float pre   = __shfl_sync(FULL, excl, rep);   // prefix for own group
        float lself = __shfl_sync(FULL, la,   rep);   // own group's log-att
        float total = __shfl_sync(FULL, incl, 31);    // sum over all 8

        float e0 = __expf(pre);
        float e1 = __expf(pre + lself);
        float w  = T * (e0 - e1);                 // = T*exp(pre)*(1-exp(la))

        c_acc += (sub == 3) ? 0.f : w * fmaxf(fin + 0.5f, 0.f);
        T *= __expf(total);

        // T-cutoff on odd iterations only (leftover < ~2e-5 abs; extra
        // processed iterations are correctness-neutral).
        if ((it & 1) && T < 1e-5f) break;
    }

    // Sum each color across the 8 groups: lanes congruent mod 4 share a color.
    c_acc += __shfl_xor_sync(FULL, c_acc, 4);
    c_acc += __shfl_xor_sync(FULL, c_acc, 8);
    c_acc += __shfl_xor_sync(FULL, c_acc, 16);

    if (lane < 3)
        out[gw*3 + lane] = c_acc + T;   // + T_final * EMPTY_BRIGHT (=1)
}

// ---------------------------------------------------------------------------
extern "C" void kernel_launch(void* const* d_in, const int* in_sizes, int n_in,
                              void* d_out, int out_size)
{
    const float* origins = (const float*)d_in[0];   // [NRAYS,3]
    const float* dirs    = (const float*)d_in[1];   // [NRAYS,3]
    const float* density = (const float*)d_in[2];   // [128^3]
    const float* sh      = (const float*)d_in[3];   // [128^3,27]
    float* out = (float*)d_out;                     // [NRAYS,3]

    repack_grid<<<NVOX / VPB, 256>>>(sh, density);
    render_kernel<<<(NRAYS * 32) / 64, 64>>>(origins, dirs, out);
}

// round 16
// speedup vs baseline: 1.1098x; 1.0527x over previous
#include <cuda_runtime.h>
#include <cuda_fp16.h>
#include <cstdint>

#define RESO    128
#define NRAYS   16384
#define NSAMP   192
#define STEP    0.5f
#define NVOX    (RESO*RESO*RESO)
#define VPB     128     // voxels per repack block

// Padded fp16 grid: 32 halves = 64B per voxel (4 uint4).
// slots [0..26] = SH channels, [27] = density (fp16), [28..31] = zero padding.
__device__ uint4 g_grid4[NVOX * 4];     // NVOX * 64B

// ---------------------------------------------------------------------------
// Pass 0: repack via two-stage smem transpose.
// Stage A: coalesced float4 GMEM reads -> float4 smem stores (conflict-free).
// Stage B: one thread per output uint4: 8 scalar LDS (bank-permutation
// conflict-free), 4x cvt.f16x2, one coalesced STG.128. No div/mod anywhere.
// ---------------------------------------------------------------------------
__global__ void __launch_bounds__(256)
repack_grid(const float* __restrict__ sh, const float* __restrict__ density)
{
    __shared__ float smf[VPB * 27];     // 13824 B raw float stage
    int tid = threadIdx.x;
    size_t base = (size_t)blockIdx.x * VPB;

    // Stage A: 864 float4 per block, fully coalesced both sides.
    const float4* src = (const float4*)(sh + base * 27);
    float4* dstf = (float4*)smf;
#pragma unroll
    for (int k = 0; k < 3; ++k)
        dstf[tid + k * 256] = __ldg(src + tid + k * 256);
    if (tid < VPB * 27 / 4 - 768)
        dstf[tid + 768] = __ldg(src + tid + 768);
    __syncthreads();

    // Stage B: 512 output uint4 per block (4 per voxel).
    uint4* gout = g_grid4 + base * 4;
#pragma unroll
    for (int k = 0; k < 2; ++k) {
        int i = tid + k * 256;
        int v = i >> 2, j = i & 3;
        const float* f = smf + v * 27 + 8 * j;
        float x0, x1, x2, x3, x4, x5, x6, x7;
        if (j < 3) {
            x0 = f[0]; x1 = f[1]; x2 = f[2]; x3 = f[3];
            x4 = f[4]; x5 = f[5]; x6 = f[6]; x7 = f[7];
        } else {    // halves 24..31: ch24..26, density, zero padding
            x0 = f[0]; x1 = f[1]; x2 = f[2];
            x3 = __ldg(density + base + v);
            x4 = x5 = x6 = x7 = 0.f;
        }
        __half2 h01 = __floats2half2_rn(x0, x1);
        __half2 h23 = __floats2half2_rn(x2, x3);
        __half2 h45 = __floats2half2_rn(x4, x5);
        __half2 h67 = __floats2half2_rn(x6, x7);
        uint4 o;
        o.x = *reinterpret_cast<unsigned int*>(&h01);
        o.y = *reinterpret_cast<unsigned int*>(&h23);
        o.z = *reinterpret_cast<unsigned int*>(&h45);
        o.w = *reinterpret_cast<unsigned int*>(&h67);
        gout[i] = o;
    }
}

// ---------------------------------------------------------------------------
// Pass 1: render. One warp per ray (one warp per 32-thread block); 8 samples
// in flight, 4 lanes per sample. Lane sub (0..3) loads channels [8sub..8sub+7]
// via one LDG.128 per corner (fp16 HFMA2 accumulation). 3-shuffle transpose-
// butterfly -> lane sub owns color sub; 3-step warp scan + exp-before-shuffle
// gives transmittance prefixes with 2 exps. Analytic warp-uniform trip count
// (exact per-sample inb predicate retained). T-cutoff on odd iterations only.
// ---------------------------------------------------------------------------
__global__ void __launch_bounds__(32, 28)
render_kernel(const float* __restrict__ origins,
              const float* __restrict__ dirs,
              float* __restrict__ out)
{
    const unsigned FULL = 0xFFFFFFFFu;
    int gw   = blockIdx.x;          // ray id (one warp per block)
    int lane = threadIdx.x & 31;
    int grp = lane >> 2;       // sample-in-flight (0..7)
    int sub = lane & 3;        // channel-octet slot / color owner (0..3)

    float ox = origins[gw*3+0], oy = origins[gw*3+1], oz = origins[gw*3+2];
    float dx = dirs[gw*3+0],    dy = dirs[gw*3+1],    dz = dirs[gw*3+2];

    // Analytic ray-box exit (origins interior; box [0,127]^3). Conservative
    // ~2-sample margin dwarfs divide error; exact inb check keeps per-sample
    // classification identical.
    float tx = (fabsf(dx) > 1e-9f) ? __fdividef((dx > 0.f ? 127.f : 0.f) - ox, dx) : 1e9f;
    float ty = (fabsf(dy) > 1e-9f) ? __fdividef((dy > 0.f ? 127.f : 0.f) - oy, dy) : 1e9f;
    float tz = (fabsf(dz) > 1e-9f) ? __fdividef((dz > 0.f ? 127.f : 0.f) - oz, dz) : 1e9f;
    float t_exit = fminf(tx, fminf(ty, tz));
    int   s_hi   = (int)(2.f * t_exit + 2.f);
    int   n_it   = min(NSAMP / 8, (s_hi >> 3) + 1);   // warp-uniform

    // Real SH degree-2 basis (svox2 convention)
    float basis[9];
    basis[0] =  0.28209479177387814f;
    basis[1] = -0.4886025119029199f * dy;
    basis[2] =  0.4886025119029199f * dz;
    basis[3] = -0.4886025119029199f * dx;
    basis[4] =  1.0925484305920792f * dx * dy;
    basis[5] = -1.0925484305920792f * dy * dz;
    basis[6] =  0.31539156525252005f * (2.f*dz*dz - dx*dx - dy*dy);
    basis[7] = -1.0925484305920792f * dx * dz;
    basis[8] =  0.5462742152960396f * (dx*dx - dy*dy);

    // Two-segment channel routing: lane sub owns channels [8sub..8sub+7],
    // spanning at most 2 consecutive colors (R<9, G<18, B<27, 27=sigma).
    float cA[8], cB[8];
    {
        int chA = 8*sub;
        int chB = min(8*sub + 7, 27);
        int colA = chA < 9 ? 0 : (chA < 18 ? 1 : (chA < 27 ? 2 : 3));
        int colB = chB < 9 ? 0 : (chB < 18 ? 1 : (chB < 27 ? 2 : 3));
#pragma unroll
        for (int m = 0; m < 8; m++) {
            int ch = 8*sub + m;
            int col = ch < 9 ? 0 : (ch < 18 ? 1 : (ch < 27 ? 2 : (ch == 27 ? 3 : -1)));
            float bk = (ch < 27) ? basis[ch % 9] : (ch == 27 ? 1.f : 0.f);
            cA[m] = (col == colA) ? bk : 0.f;
            cB[m] = (col == colB && colB != colA) ? bk : 0.f;
        }
        // sub0: A=R | sub1: A=R,B=G | sub2: A=G,B=B | sub3: A=B,B=sigma
    }

    const uint4* __restrict__ gh = g_grid4;   // voxel = 4 uint4

    float T = 1.f;
    float c_acc = 0.f;      // lane sub accumulates color sub (sub3: unused)

    for (int it = 0; it < n_it; ++it) {
        int   s = it*8 + grp;
        float t = ((float)s + 0.5f) * STEP;
        float px = fmaf(t, dx, ox);
        float py = fmaf(t, dy, oy);
        float pz = fmaf(t, dz, oz);
        bool inb = (px >= 0.f) && (px <= 127.f) &&
                   (py >= 0.f) && (py <= 127.f) &&
                   (pz >= 0.f) && (pz <= 127.f);

        float fx = floorf(px), fy = floorf(py), fz = floorf(pz);
        float rx = px - fx,    ry = py - fy,    rz = pz - fz;
        int ix = min(max((int)fx, 0), RESO - 2);
        int iy = min(max((int)fy, 0), RESO - 2);
        int iz = min(max((int)fz, 0), RESO - 2);
        float wx0 = 1.f - rx, wy0 = 1.f - ry, wz0 = 1.f - rz;

        __half2 acc0 = __float2half2_rn(0.f), acc1 = acc0;
        __half2 acc2 = acc0, acc3 = acc0;
        if (inb) {
            int vox = (((ix << 7) | iy) << 7) | iz;
            const uint4* p = gh + vox * 4 + sub;
#pragma unroll
            for (int c = 0; c < 8; ++c) {
                float w = ((c & 4) ? rx : wx0) *
                          ((c & 2) ? ry : wy0) *
                          ((c & 1) ? rz : wz0);
                __half2 wh = __float2half2_rn(w);
                uint4 u = __ldg(p + ((c & 4) ? (RESO*RESO*4) : 0)
                                  + ((c & 2) ? (RESO*4)      : 0)
                                  + ((c & 1) ? 4             : 0));
                acc0 = __hfma2(wh, *(const __half2*)&u.x, acc0);
                acc1 = __hfma2(wh, *(const __half2*)&u.y, acc1);
                acc2 = __hfma2(wh, *(const __half2*)&u.z, acc2);
                acc3 = __hfma2(wh, *(const __half2*)&u.w, acc3);
            }
        }
        float2 g0 = __half22float2(acc0);
        float2 g1 = __half22float2(acc1);
        float2 g2 = __half22float2(acc2);
        float2 g3 = __half22float2(acc3);
        float f0=g0.x, f1=g0.y, f2=g1.x, f3=g1.y, f4=g2.x, f5=g2.y, f6=g3.x, f7=g3.y;

        float pA = f0*cA[0]+f1*cA[1]+f2*cA[2]+f3*cA[3]+f4*cA[4]+f5*cA[5]+f6*cA[6]+f7*cA[7];
        float pB = f0*cB[0]+f1*cB[1]+f2*cB[2]+f3*cB[3]+f4*cB[4]+f5*cB[5]+f6*cB[6]+f7*cB[7];

        // Map segment partials to per-color contributions v0..v3 (R,G,B,sigma).
        float v0 = (sub <= 1) ? pA : 0.f;
        float v1 = (sub == 1) ? pB : ((sub == 2) ? pA : 0.f);
        float v2 = (sub == 2) ? pB : ((sub == 3) ? pA : 0.f);
        float v3 = (sub == 3) ? pB : 0.f;

        // Transpose-butterfly over the 4-lane group: lane sub ends with the
        // group total of v_sub. 3 shuffles.
        bool b0 = sub & 1, b1 = sub & 2;
        float sA = __shfl_xor_sync(FULL, b0 ? v0 : v1, 1);
        float A  = (b0 ? v1 : v0) + sA;
        float sB = __shfl_xor_sync(FULL, b0 ? v2 : v3, 1);
        float B  = (b0 ? v3 : v2) + sB;
        float sF = __shfl_xor_sync(FULL, b1 ? A : B, 2);
        float fin = (b1 ? B : A) + sF;           // lane sub: total of v_sub

        // sigma lives on sub==3 lanes (group-uniform inb).
        float sigma = (inb && fin > 1e-10f) ? fin : 0.f;
        float la = -sigma * STEP;                // valid on the sub==3 chain

        // Inclusive scan of la over the stride-4 sub==3 chain.
        float incl = la;
        float u1 = __shfl_up_sync(FULL, incl, 4);  if (lane >= 4)  incl += u1;
        float u2 = __shfl_up_sync(FULL, incl, 8);  if (lane >= 8)  incl += u2;
        float u3 = __shfl_up_sync(FULL, incl, 16); if (lane >= 16) incl += u3;
        float excl = incl - la;

        // Exponentiate on-chain BEFORE broadcasting (2 exps, independent).
        float ei = __expf(incl);     // exp(inclusive prefix)
        float ee = __expf(excl);     // exp(exclusive prefix)

        int rep = lane | 3;
        float e0 = __shfl_sync(FULL, ee, rep);    // exp(prefix) for own group
        float e1 = __shfl_sync(FULL, ei, rep);    // exp(prefix+own la)
        float eT = __shfl_sync(FULL, ei, 31);     // exp(total of all 8)

        float w = T * (e0 - e1);                  // = T*exp(pre)*(1-exp(la))
        c_acc += (sub == 3) ? 0.f : w * fmaxf(fin + 0.5f, 0.f);
        T *= eT;

        // T-cutoff on odd iterations only (leftover < ~2e-5 abs; extra
        // processed iterations are correctness-neutral).
        if ((it & 1) && T < 1e-5f) break;
    }

    // Sum each color across the 8 groups: lanes congruent mod 4 share a color.
    c_acc += __shfl_xor_sync(FULL, c_acc, 4);
    c_acc += __shfl_xor_sync(FULL, c_acc, 8);
    c_acc += __shfl_xor_sync(FULL, c_acc, 16);

    if (lane < 3)
        out[gw*3 + lane] = c_acc + T;   // + T_final * EMPTY_BRIGHT (=1)
}

// ---------------------------------------------------------------------------
extern "C" void kernel_launch(void* const* d_in, const int* in_sizes, int n_in,
                              void* d_out, int out_size)
{
    const float* origins = (const float*)d_in[0];   // [NRAYS,3]
    const float* dirs    = (const float*)d_in[1];   // [NRAYS,3]
    const float* density = (const float*)d_in[2];   // [128^3]
    const float* sh      = (const float*)d_in[3];   // [128^3,27]
    float* out = (float*)d_out;                     // [NRAYS,3]

    repack_grid<<<NVOX / VPB, 256>>>(sh, density);
    render_kernel<<<NRAYS, 32>>>(origins, dirs, out);
}